// round 7
// baseline (speedup 1.0000x reference)
#include <cuda_runtime.h>
#include <math.h>

#define B_  2
#define T_  2048
#define D_  1024
#define H_  16
#define DH_ 64
#define M_  (B_ * T_)          // 4096 rows in every GEMM

// ---------------------------------------------------------------------------
// Scratch (device globals: allocation-free, graph-capture safe)
// ---------------------------------------------------------------------------
__device__ __align__(16) float g_q[B_ * H_ * T_ * DH_];    // (B,H,T,DH)
__device__ __align__(16) float g_k[B_ * H_ * T_ * DH_];
__device__ __align__(16) float g_v[B_ * H_ * T_ * DH_];
__device__ __align__(16) float g_attn[B_ * T_ * D_];       // (B,T,D)

// ---------------------------------------------------------------------------
// GEMM: Y = A(4096x1024) @ W(1024x1024)
// BM=128, BN=64, BK=16, 256 threads, each computes 8x4.
// MODE 0: Y in (M,N) row-major (i.e. (B,T,D))
// MODE 1: Y scattered to (B,H,T,DH) head-major layout
// ---------------------------------------------------------------------------
template <int MODE>
__global__ __launch_bounds__(256) void gemm_kernel(const float* __restrict__ A,
                                                   const float* __restrict__ W,
                                                   float* __restrict__ Y) {
    __shared__ float As[16][132];   // transposed A tile: As[k][m], padded
    __shared__ float Bs[16][64];    // Bs[k][n]

    const int tid = threadIdx.x;
    const int tx = tid & 15;        // 0..15 -> n
    const int ty = tid >> 4;        // 0..15 -> m
    const int m0 = blockIdx.y * 128;
    const int n0 = blockIdx.x * 64;

    float acc[8][4];
#pragma unroll
    for (int i = 0; i < 8; i++)
#pragma unroll
        for (int j = 0; j < 4; j++) acc[i][j] = 0.f;

    const int a_row = tid >> 2;          // 0..63 (+64 on 2nd chunk)
    const int a_k4  = (tid & 3) * 4;     // 0,4,8,12
    const int b_kr  = tid >> 4;          // 0..15
    const int b_n4  = (tid & 15) * 4;    // 0..60

    for (int kt = 0; kt < 1024; kt += 16) {
        // A tile 128x16 (2 float4 per thread), stored transposed
#pragma unroll
        for (int c = 0; c < 2; c++) {
            const int row = a_row + c * 64;
            float4 v = *(const float4*)&A[(size_t)(m0 + row) * 1024 + kt + a_k4];
            As[a_k4 + 0][row] = v.x;
            As[a_k4 + 1][row] = v.y;
            As[a_k4 + 2][row] = v.z;
            As[a_k4 + 3][row] = v.w;
        }
        // B tile 16x64 (1 float4 per thread)
        *(float4*)&Bs[b_kr][b_n4] =
            *(const float4*)&W[(size_t)(kt + b_kr) * 1024 + n0 + b_n4];
        __syncthreads();

#pragma unroll
        for (int k = 0; k < 16; k++) {
            const float4 b4 = *(const float4*)&Bs[k][tx * 4];
            const float4 a0 = *(const float4*)&As[k][ty * 8];
            const float4 a1 = *(const float4*)&As[k][ty * 8 + 4];
            const float a[8] = {a0.x, a0.y, a0.z, a0.w, a1.x, a1.y, a1.z, a1.w};
            const float b[4] = {b4.x, b4.y, b4.z, b4.w};
#pragma unroll
            for (int i = 0; i < 8; i++)
#pragma unroll
                for (int j = 0; j < 4; j++)
                    acc[i][j] = fmaf(a[i], b[j], acc[i][j]);
        }
        __syncthreads();
    }

#pragma unroll
    for (int i = 0; i < 8; i++) {
        const int m = m0 + ty * 8 + i;
        const int n = n0 + tx * 4;
        float4 r = make_float4(acc[i][0], acc[i][1], acc[i][2], acc[i][3]);
        if (MODE == 0) {
            *(float4*)&Y[(size_t)m * 1024 + n] = r;
        } else {
            const int b  = m >> 11;        // /T_
            const int t  = m & 2047;
            const int h  = n >> 6;         // /DH_ (block-aligned: constant per CTA)
            const int dh = n & 63;
            *(float4*)&Y[(((size_t)(b * H_ + h)) * T_ + t) * DH_ + dh] = r;
        }
    }
}

// ---------------------------------------------------------------------------
// Flash attention, fp32. One CTA per (bh, 64-row q block).
// 256 threads (16x16), each owns a 4x4 patch of the 64x64 S tile and a 4x4
// patch of the 64x64 O tile. Online softmax, causal block skipping.
// ---------------------------------------------------------------------------
#define APAD 68   // row stride (floats) in smem tiles: 16B-aligned, conflict-light

__global__ __launch_bounds__(256) void attn_kernel(float* __restrict__ Yattn) {
    extern __shared__ float sm[];
    float* Qs = sm;                 // 64 * APAD
    float* Ks = sm + 64 * APAD;
    float* Vs = sm + 2 * 64 * APAD;
    float* Ps = sm + 3 * 64 * APAD;

    const int qb = gridDim.x - 1 - blockIdx.x;   // heavy blocks first
    const int bh = blockIdx.y;
    const float* Q  = g_q + (size_t)bh * T_ * DH_;
    const float* Kp = g_k + (size_t)bh * T_ * DH_;
    const float* Vp = g_v + (size_t)bh * T_ * DH_;

    const int tid = threadIdx.x;
    const int tx = tid & 15;   // -> 4 k-cols / 4 dh-cols
    const int ty = tid >> 4;   // -> 4 q-rows

    // Load Q block (64x64): 4 float4 per thread
#pragma unroll
    for (int it = 0; it < 4; it++) {
        const int idx = tid + it * 256;
        const int row = idx >> 4;
        const int c4  = (idx & 15) * 4;
        *(float4*)&Qs[row * APAD + c4] =
            *(const float4*)&Q[(size_t)(qb * 64 + row) * DH_ + c4];
    }

    float o[4][4];
    float mrow[4], lrow[4];
#pragma unroll
    for (int i = 0; i < 4; i++) {
        mrow[i] = -1e30f;
        lrow[i] = 0.f;
#pragma unroll
        for (int j = 0; j < 4; j++) o[i][j] = 0.f;
    }

    for (int kb = 0; kb <= qb; kb++) {
        // Load K & V blocks
#pragma unroll
        for (int it = 0; it < 4; it++) {
            const int idx = tid + it * 256;
            const int row = idx >> 4;
            const int c4  = (idx & 15) * 4;
            *(float4*)&Ks[row * APAD + c4] =
                *(const float4*)&Kp[(size_t)(kb * 64 + row) * DH_ + c4];
            *(float4*)&Vs[row * APAD + c4] =
                *(const float4*)&Vp[(size_t)(kb * 64 + row) * DH_ + c4];
        }
        __syncthreads();

        // S = Q @ K^T (4x4 patch)
        float s[4][4];
#pragma unroll
        for (int i = 0; i < 4; i++)
#pragma unroll
            for (int j = 0; j < 4; j++) s[i][j] = 0.f;

#pragma unroll 8
        for (int k = 0; k < 64; k++) {
            float qv[4], kv[4];
#pragma unroll
            for (int i = 0; i < 4; i++) qv[i] = Qs[(ty * 4 + i) * APAD + k];
#pragma unroll
            for (int j = 0; j < 4; j++) kv[j] = Ks[(tx * 4 + j) * APAD + k];
#pragma unroll
            for (int i = 0; i < 4; i++)
#pragma unroll
                for (int j = 0; j < 4; j++)
                    s[i][j] = fmaf(qv[i], kv[j], s[i][j]);
        }

        // Scale + causal mask + online softmax (row state replicated across tx)
        const bool diag = (kb == qb);
#pragma unroll
        for (int i = 0; i < 4; i++) {
            const int qrow = qb * 64 + ty * 4 + i;
            float rmax = -1e30f;
#pragma unroll
            for (int j = 0; j < 4; j++) {
                float v = s[i][j] * 0.125f;                  // 1/sqrt(64)
                if (diag && (kb * 64 + tx * 4 + j) > qrow) v = -1e30f;
                s[i][j] = v;
                rmax = fmaxf(rmax, v);
            }
#pragma unroll
            for (int off = 8; off >= 1; off >>= 1)
                rmax = fmaxf(rmax, __shfl_xor_sync(0xffffffffu, rmax, off));

            const float mnew  = fmaxf(mrow[i], rmax);
            const float alpha = __expf(mrow[i] - mnew);
            float rsum = 0.f;
#pragma unroll
            for (int j = 0; j < 4; j++) {
                const float p = __expf(s[i][j] - mnew);
                s[i][j] = p;
                rsum += p;
            }
#pragma unroll
            for (int off = 8; off >= 1; off >>= 1)
                rsum += __shfl_xor_sync(0xffffffffu, rsum, off);

            lrow[i] = lrow[i] * alpha + rsum;
            mrow[i] = mnew;
#pragma unroll
            for (int j = 0; j < 4; j++) o[i][j] *= alpha;
        }

        // Stage P into smem (need full rows for P @ V)
#pragma unroll
        for (int i = 0; i < 4; i++)
#pragma unroll
            for (int j = 0; j < 4; j++)
                Ps[(ty * 4 + i) * APAD + tx * 4 + j] = s[i][j];
        __syncthreads();

        // O += P @ V
#pragma unroll 8
        for (int kk = 0; kk < 64; kk++) {
            float pv[4], vv[4];
#pragma unroll
            for (int i = 0; i < 4; i++) pv[i] = Ps[(ty * 4 + i) * APAD + kk];
#pragma unroll
            for (int j = 0; j < 4; j++) vv[j] = Vs[kk * APAD + tx * 4 + j];
#pragma unroll
            for (int i = 0; i < 4; i++)
#pragma unroll
                for (int j = 0; j < 4; j++)
                    o[i][j] = fmaf(pv[i], vv[j], o[i][j]);
        }
        __syncthreads();   // protect Ks/Vs/Ps before next iteration's loads
    }

    // Normalize and write to (B,T,D) scratch
    const int b = bh >> 4;   // /H_
    const int h = bh & 15;
#pragma unroll
    for (int i = 0; i < 4; i++) {
        const int t = qb * 64 + ty * 4 + i;
        const float inv = 1.f / lrow[i];
        float4 r = make_float4(o[i][0] * inv, o[i][1] * inv,
                               o[i][2] * inv, o[i][3] * inv);
        *(float4*)&Yattn[((size_t)(b * T_ + t)) * D_ + h * DH_ + tx * 4] = r;
    }
}

// ---------------------------------------------------------------------------
// Host launcher (graph-capturable: kernel launches + immediate-mode APIs only)
// ---------------------------------------------------------------------------
extern "C" void kernel_launch(void* const* d_in, const int* in_sizes, int n_in,
                              void* d_out, int out_size) {
    (void)in_sizes; (void)n_in; (void)out_size;
    const float* x  = (const float*)d_in[0];
    const float* Wq = (const float*)d_in[1];
    const float* Wk = (const float*)d_in[2];
    const float* Wv = (const float*)d_in[3];
    const float* Wo = (const float*)d_in[4];
    float* out = (float*)d_out;

    float *q, *k, *v, *attn;
    cudaGetSymbolAddress((void**)&q,    g_q);
    cudaGetSymbolAddress((void**)&k,    g_k);
    cudaGetSymbolAddress((void**)&v,    g_v);
    cudaGetSymbolAddress((void**)&attn, g_attn);

    const dim3 ggrid(1024 / 64, M_ / 128);   // (16, 32) = 512 CTAs
    gemm_kernel<1><<<ggrid, 256>>>(x, Wq, q);
    gemm_kernel<1><<<ggrid, 256>>>(x, Wk, k);
    gemm_kernel<1><<<ggrid, 256>>>(x, Wv, v);

    const int smem = 4 * 64 * APAD * (int)sizeof(float);   // 69632 B
    cudaFuncSetAttribute(attn_kernel,
                         cudaFuncAttributeMaxDynamicSharedMemorySize, smem);
    const dim3 agrid(T_ / 64, B_ * H_);      // (32, 32) = 1024 CTAs
    attn_kernel<<<agrid, 256, smem>>>(attn);

    gemm_kernel<0><<<ggrid, 256>>>(attn, Wo, out);
}

// round 8
// speedup vs baseline: 1.2875x; 1.2875x over previous
#include <cuda_runtime.h>
#include <math.h>

#define B_  2
#define T_  2048
#define D_  1024
#define H_  16
#define DH_ 64
#define M_  (B_ * T_)          // 4096 rows in every GEMM

typedef unsigned long long u64;

// ---------------------------------------------------------------------------
// f32x2 packed-FMA helpers (Blackwell sm_100+: fma.rn.f32x2 / mul.rn.f32x2)
// ---------------------------------------------------------------------------
__device__ __forceinline__ u64 pk1(float v) {
    u64 d; asm("mov.b64 %0, {%1, %1};" : "=l"(d) : "f"(v)); return d;
}
__device__ __forceinline__ u64 pk2(float lo, float hi) {
    u64 d; asm("mov.b64 %0, {%1, %2};" : "=l"(d) : "f"(lo), "f"(hi)); return d;
}
__device__ __forceinline__ float2 upk(u64 d) {
    float2 f; asm("mov.b64 {%0, %1}, %2;" : "=f"(f.x), "=f"(f.y) : "l"(d)); return f;
}
__device__ __forceinline__ void fma2(u64& c, u64 a, u64 b) {
    asm("fma.rn.f32x2 %0, %1, %2, %3;" : "=l"(c) : "l"(a), "l"(b), "l"(c));
}
__device__ __forceinline__ u64 mul2(u64 a, u64 b) {
    u64 d; asm("mul.rn.f32x2 %0, %1, %2;" : "=l"(d) : "l"(a), "l"(b)); return d;
}

// ---------------------------------------------------------------------------
// Scratch (device globals: allocation-free, graph-capture safe)
// ---------------------------------------------------------------------------
__device__ __align__(16) float g_q[B_ * H_ * T_ * DH_];    // (B,H,T,DH)
__device__ __align__(16) float g_k[B_ * H_ * T_ * DH_];
__device__ __align__(16) float g_v[B_ * H_ * T_ * DH_];
__device__ __align__(16) float g_attn[B_ * T_ * D_];       // (B,T,D)

// ---------------------------------------------------------------------------
// GEMM: Y = A(4096x1024) @ W(1024x1024)
// BM=128, BN=64, BK=16, 256 threads, each computes 8x4 via f32x2 pairs.
// MODE 0: Y in (M,N) row-major.  MODE 1: Y scattered to (B,H,T,DH).
// ---------------------------------------------------------------------------
template <int MODE>
__global__ __launch_bounds__(256) void gemm_kernel(const float* __restrict__ A,
                                                   const float* __restrict__ W,
                                                   float* __restrict__ Y) {
    __shared__ __align__(16) float As[16][132];   // transposed A tile: As[k][m]
    __shared__ __align__(16) float Bs[16][64];    // Bs[k][n]

    const int tid = threadIdx.x;
    const int tx = tid & 15;        // n
    const int ty = tid >> 4;        // m
    const int m0 = blockIdx.y * 128;
    const int n0 = blockIdx.x * 64;

    u64 acc2[8][2];
#pragma unroll
    for (int i = 0; i < 8; i++) { acc2[i][0] = 0ull; acc2[i][1] = 0ull; }

    const int a_row = tid >> 2;
    const int a_k4  = (tid & 3) * 4;
    const int b_kr  = tid >> 4;
    const int b_n4  = (tid & 15) * 4;

    for (int kt = 0; kt < 1024; kt += 16) {
#pragma unroll
        for (int c = 0; c < 2; c++) {
            const int row = a_row + c * 64;
            float4 v = *(const float4*)&A[(size_t)(m0 + row) * 1024 + kt + a_k4];
            As[a_k4 + 0][row] = v.x;
            As[a_k4 + 1][row] = v.y;
            As[a_k4 + 2][row] = v.z;
            As[a_k4 + 3][row] = v.w;
        }
        *(float4*)&Bs[b_kr][b_n4] =
            *(const float4*)&W[(size_t)(kt + b_kr) * 1024 + n0 + b_n4];
        __syncthreads();

#pragma unroll
        for (int k = 0; k < 16; k++) {
            const ulonglong2 bv = *(const ulonglong2*)&Bs[k][tx * 4];
            const float4 a0 = *(const float4*)&As[k][ty * 8];
            const float4 a1 = *(const float4*)&As[k][ty * 8 + 4];
            const float a[8] = {a0.x, a0.y, a0.z, a0.w, a1.x, a1.y, a1.z, a1.w};
#pragma unroll
            for (int i = 0; i < 8; i++) {
                const u64 ad = pk1(a[i]);
                fma2(acc2[i][0], ad, bv.x);
                fma2(acc2[i][1], ad, bv.y);
            }
        }
        __syncthreads();
    }

#pragma unroll
    for (int i = 0; i < 8; i++) {
        const int m = m0 + ty * 8 + i;
        const int n = n0 + tx * 4;
        const float2 lo = upk(acc2[i][0]);
        const float2 hi = upk(acc2[i][1]);
        float4 r = make_float4(lo.x, lo.y, hi.x, hi.y);
        if (MODE == 0) {
            *(float4*)&Y[(size_t)m * 1024 + n] = r;
        } else {
            const int b  = m >> 11;
            const int t  = m & 2047;
            const int h  = n >> 6;
            const int dh = n & 63;
            *(float4*)&Y[(((size_t)(b * H_ + h)) * T_ + t) * DH_ + dh] = r;
        }
    }
}

// ---------------------------------------------------------------------------
// Flash attention, fp32, f32x2 math. One CTA per (bh, 128-row q block).
// 256 threads (16x16). S tile 128x128, each thread an 8x8 patch.
// Q,K stored k-major (transposed) with XOR-16B swizzle; P stored transposed
// (PsT[kk][q], same swizzle) so PV reads contiguous q-pairs for f32x2.
// ---------------------------------------------------------------------------
#define BQ 128
#define BK 128

// smem float offsets
#define OFF_Q  0                        // QsT [64][128]
#define OFF_K  8192                     // KsT [64][128]
#define OFF_V  16384                    // Vs  [128][68]
#define OFF_P  25088                    // PsT [128][128]
#define SMEM_FLOATS (25088 + 128 * 128) // 41472 floats = 165888 B

__global__ __launch_bounds__(256) void attn_kernel(float* __restrict__ Yattn) {
    extern __shared__ __align__(16) float sm[];
    float* QsT = sm + OFF_Q;
    float* KsT = sm + OFF_K;
    float* Vs  = sm + OFF_V;
    float* PsT = sm + OFF_P;

    const int qb = gridDim.x - 1 - blockIdx.x;   // heavy blocks first
    const int bh = blockIdx.y;
    const float* Q  = g_q + (size_t)bh * T_ * DH_ + (size_t)qb * BQ * DH_;
    const float* Kp = g_k + (size_t)bh * T_ * DH_;
    const float* Vp = g_v + (size_t)bh * T_ * DH_;

    const int tid = threadIdx.x;
    const int tx = tid & 15;   // 8 kk-cols (S) / 4 dh-cols (PV)
    const int ty = tid >> 4;   // 8 q-rows

    // ---- Load Q transposed with swizzle: QsT[k][seq ^ sw(k)], sw(k)=((k>>2)&7)<<2
#pragma unroll
    for (int it = 0; it < 8; it++) {
        const int idx = tid + it * 256;
        const int row = idx >> 4;            // seq 0..127
        const int c4  = (idx & 15) * 4;      // dh base (= k base)
        const int pc  = row ^ ((idx & 7) << 2);   // (c4>>2)&7 == idx&7
        const float4 v = *(const float4*)&Q[row * 64 + c4];
        QsT[(c4 + 0) * 128 + pc] = v.x;
        QsT[(c4 + 1) * 128 + pc] = v.y;
        QsT[(c4 + 2) * 128 + pc] = v.z;
        QsT[(c4 + 3) * 128 + pc] = v.w;
    }

    u64 o2[4][4];                      // O pairs along q: rows (ty*8+2ip, +1), col tx*4+j
    float mrow[8], lrow[8];
#pragma unroll
    for (int ip = 0; ip < 4; ip++)
#pragma unroll
        for (int j = 0; j < 4; j++) o2[ip][j] = 0ull;
#pragma unroll
    for (int i = 0; i < 8; i++) { mrow[i] = -1e30f; lrow[i] = 0.f; }

    for (int kb = 0; kb <= qb; kb++) {
        __syncthreads();   // prior iteration's PV reads of KsT/Vs/PsT complete

        // ---- Load K (transposed+swizzled) and V (straight) tiles
        const float* Kt = Kp + (size_t)kb * BK * DH_;
        const float* Vt = Vp + (size_t)kb * BK * DH_;
#pragma unroll
        for (int it = 0; it < 8; it++) {
            const int idx = tid + it * 256;
            const int row = idx >> 4;
            const int c4  = (idx & 15) * 4;
            const int pc  = row ^ ((idx & 7) << 2);
            const float4 kv = *(const float4*)&Kt[row * 64 + c4];
            KsT[(c4 + 0) * 128 + pc] = kv.x;
            KsT[(c4 + 1) * 128 + pc] = kv.y;
            KsT[(c4 + 2) * 128 + pc] = kv.z;
            KsT[(c4 + 3) * 128 + pc] = kv.w;
            const float4 vv = *(const float4*)&Vt[row * 64 + c4];
            *(float4*)&Vs[row * 68 + c4] = vv;
        }
        __syncthreads();

        // ---- S = Q @ K^T : 8x8 patch as 8 x 4 f32x2 (pairs along kk)
        u64 s2[8][4];
#pragma unroll
        for (int i = 0; i < 8; i++)
#pragma unroll
            for (int jp = 0; jp < 4; jp++) s2[i][jp] = 0ull;

#pragma unroll 4
        for (int k = 0; k < 64; k++) {
            const int swk = ((k >> 2) & 7) << 2;
            const float4 q0 = *(const float4*)&QsT[k * 128 + ((ty * 8) ^ swk)];
            const float4 q1 = *(const float4*)&QsT[k * 128 + ((ty * 8 + 4) ^ swk)];
            const ulonglong2 k0 = *(const ulonglong2*)&KsT[k * 128 + ((tx * 8) ^ swk)];
            const ulonglong2 k1 = *(const ulonglong2*)&KsT[k * 128 + ((tx * 8 + 4) ^ swk)];
            const u64 kd[4] = {k0.x, k0.y, k1.x, k1.y};
            const float qa[8] = {q0.x, q0.y, q0.z, q0.w, q1.x, q1.y, q1.z, q1.w};
#pragma unroll
            for (int i = 0; i < 8; i++) {
                const u64 qd = pk1(qa[i]);
#pragma unroll
                for (int jp = 0; jp < 4; jp++) fma2(s2[i][jp], qd, kd[jp]);
            }
        }

        // ---- unpack, scale, mask, online softmax
        float s[8][8];
#pragma unroll
        for (int i = 0; i < 8; i++)
#pragma unroll
            for (int jp = 0; jp < 4; jp++) {
                const float2 f = upk(s2[i][jp]);
                s[i][2 * jp]     = f.x;
                s[i][2 * jp + 1] = f.y;
            }

        const bool diag = (kb == qb);
        float alpha[8];
#pragma unroll
        for (int i = 0; i < 8; i++) {
            const int qrow = ty * 8 + i;       // local row; diag block: col > row masked
            float rmax = -1e30f;
#pragma unroll
            for (int j = 0; j < 8; j++) {
                float v = s[i][j] * 0.125f;    // 1/sqrt(64)
                if (diag && (tx * 8 + j) > qrow) v = -1e30f;
                s[i][j] = v;
                rmax = fmaxf(rmax, v);
            }
#pragma unroll
            for (int off = 8; off >= 1; off >>= 1)
                rmax = fmaxf(rmax, __shfl_xor_sync(0xffffffffu, rmax, off));

            const float mnew = fmaxf(mrow[i], rmax);
            alpha[i] = __expf(mrow[i] - mnew);
            float rsum = 0.f;
#pragma unroll
            for (int j = 0; j < 8; j++) {
                const float p = __expf(s[i][j] - mnew);
                s[i][j] = p;
                rsum += p;
            }
#pragma unroll
            for (int off = 8; off >= 1; off >>= 1)
                rsum += __shfl_xor_sync(0xffffffffu, rsum, off);

            lrow[i] = lrow[i] * alpha[i] + rsum;
            mrow[i] = mnew;
        }
#pragma unroll
        for (int ip = 0; ip < 4; ip++) {
            const u64 al2 = pk2(alpha[2 * ip], alpha[2 * ip + 1]);
#pragma unroll
            for (int j = 0; j < 4; j++) o2[ip][j] = mul2(o2[ip][j], al2);
        }

        // ---- store P transposed: PsT[kk][q ^ swp(kk)], swp(kk)=((kk>>3)&7)<<2
        {
            const int swp = (tx & 7) << 2;     // kk = tx*8+j -> (kk>>3)&7 == tx&7
#pragma unroll
            for (int j = 0; j < 8; j++) {
                float4 w0 = make_float4(s[0][j], s[1][j], s[2][j], s[3][j]);
                float4 w1 = make_float4(s[4][j], s[5][j], s[6][j], s[7][j]);
                *(float4*)&PsT[(tx * 8 + j) * 128 + ((ty * 8) ^ swp)]     = w0;
                *(float4*)&PsT[(tx * 8 + j) * 128 + ((ty * 8 + 4) ^ swp)] = w1;
            }
        }
        __syncthreads();

        // ---- O += P @ V : o2 pairs along q, f32x2
#pragma unroll 4
        for (int kk = 0; kk < 128; kk++) {
            const int swp = ((kk >> 3) & 7) << 2;
            const ulonglong2 p01 = *(const ulonglong2*)&PsT[kk * 128 + ((ty * 8) ^ swp)];
            const ulonglong2 p23 = *(const ulonglong2*)&PsT[kk * 128 + ((ty * 8 + 4) ^ swp)];
            const u64 pd[4] = {p01.x, p01.y, p23.x, p23.y};
            const float4 vv = *(const float4*)&Vs[kk * 68 + tx * 4];
            const u64 vd[4] = {pk1(vv.x), pk1(vv.y), pk1(vv.z), pk1(vv.w)};
#pragma unroll
            for (int ip = 0; ip < 4; ip++)
#pragma unroll
                for (int j = 0; j < 4; j++) fma2(o2[ip][j], pd[ip], vd[j]);
        }
    }

    // ---- normalize + write (B,T,D)
    const int b = bh >> 4;
    const int h = bh & 15;
#pragma unroll
    for (int ip = 0; ip < 4; ip++) {
        const u64 li = pk2(1.f / lrow[2 * ip], 1.f / lrow[2 * ip + 1]);
        float2 c0 = upk(mul2(o2[ip][0], li));
        float2 c1 = upk(mul2(o2[ip][1], li));
        float2 c2 = upk(mul2(o2[ip][2], li));
        float2 c3 = upk(mul2(o2[ip][3], li));
        const int t0 = qb * BQ + ty * 8 + 2 * ip;
        float* base0 = &Yattn[((size_t)(b * T_ + t0)) * D_ + h * DH_ + tx * 4];
        float* base1 = &Yattn[((size_t)(b * T_ + t0 + 1)) * D_ + h * DH_ + tx * 4];
        *(float4*)base0 = make_float4(c0.x, c1.x, c2.x, c3.x);
        *(float4*)base1 = make_float4(c0.y, c1.y, c2.y, c3.y);
    }
}

// ---------------------------------------------------------------------------
// Host launcher (graph-capturable: kernel launches + immediate-mode APIs only)
// ---------------------------------------------------------------------------
extern "C" void kernel_launch(void* const* d_in, const int* in_sizes, int n_in,
                              void* d_out, int out_size) {
    (void)in_sizes; (void)n_in; (void)out_size;
    const float* x  = (const float*)d_in[0];
    const float* Wq = (const float*)d_in[1];
    const float* Wk = (const float*)d_in[2];
    const float* Wv = (const float*)d_in[3];
    const float* Wo = (const float*)d_in[4];
    float* out = (float*)d_out;

    float *q, *k, *v, *attn;
    cudaGetSymbolAddress((void**)&q,    g_q);
    cudaGetSymbolAddress((void**)&k,    g_k);
    cudaGetSymbolAddress((void**)&v,    g_v);
    cudaGetSymbolAddress((void**)&attn, g_attn);

    const dim3 ggrid(1024 / 64, M_ / 128);   // (16, 32) = 512 CTAs
    gemm_kernel<1><<<ggrid, 256>>>(x, Wq, q);
    gemm_kernel<1><<<ggrid, 256>>>(x, Wk, k);
    gemm_kernel<1><<<ggrid, 256>>>(x, Wv, v);

    const int smem = SMEM_FLOATS * (int)sizeof(float);   // 165888 B
    cudaFuncSetAttribute(attn_kernel,
                         cudaFuncAttributeMaxDynamicSharedMemorySize, smem);
    const dim3 agrid(T_ / BQ, B_ * H_);      // (16, 32) = 512 CTAs
    attn_kernel<<<agrid, 256, smem>>>(attn);

    gemm_kernel<0><<<ggrid, 256>>>(attn, Wo, out);
}

// round 10
// speedup vs baseline: 2.0486x; 1.5912x over previous
#include <cuda_runtime.h>
#include <cuda_bf16.h>
#include <cstdint>
#include <math.h>

#define B_  2
#define T_  2048
#define D_  1024
#define H_  16
#define DH_ 64
#define M_  (B_ * T_)          // 4096 rows in every GEMM

typedef unsigned long long u64;
typedef unsigned int u32;

// ---------------------------------------------------------------------------
// f32x2 packed-FMA helpers (attention kernel)
// ---------------------------------------------------------------------------
__device__ __forceinline__ u64 pk1(float v) {
    u64 d; asm("mov.b64 %0, {%1, %1};" : "=l"(d) : "f"(v)); return d;
}
__device__ __forceinline__ u64 pk2(float lo, float hi) {
    u64 d; asm("mov.b64 %0, {%1, %2};" : "=l"(d) : "f"(lo), "f"(hi)); return d;
}
__device__ __forceinline__ float2 upk(u64 d) {
    float2 f; asm("mov.b64 {%0, %1}, %2;" : "=f"(f.x), "=f"(f.y) : "l"(d)); return f;
}
__device__ __forceinline__ void fma2(u64& c, u64 a, u64 b) {
    asm("fma.rn.f32x2 %0, %1, %2, %3;" : "=l"(c) : "l"(a), "l"(b), "l"(c));
}
__device__ __forceinline__ u64 mul2(u64 a, u64 b) {
    u64 d; asm("mul.rn.f32x2 %0, %1, %2;" : "=l"(d) : "l"(a), "l"(b)); return d;
}

// ---------------------------------------------------------------------------
// Generic tensor-core PTX (sm_80+, legal under compute_103 virtual target)
// ---------------------------------------------------------------------------
__device__ __forceinline__ u32 smem_u32(const void* p) {
    u32 a;
    asm("{ .reg .u64 t; cvta.to.shared.u64 t, %1; cvt.u32.u64 %0, t; }"
        : "=r"(a) : "l"(p));
    return a;
}
__device__ __forceinline__ void ldsm4(u32& r0, u32& r1, u32& r2, u32& r3, u32 addr) {
    asm volatile("ldmatrix.sync.aligned.m8n8.x4.shared.b16 {%0,%1,%2,%3}, [%4];"
                 : "=r"(r0), "=r"(r1), "=r"(r2), "=r"(r3) : "r"(addr));
}
__device__ __forceinline__ void mma16816(float* c, const u32* a, const u32* b) {
    asm volatile("mma.sync.aligned.m16n8k16.row.col.f32.bf16.bf16.f32 "
                 "{%0,%1,%2,%3}, {%4,%5,%6,%7}, {%8,%9}, {%0,%1,%2,%3};"
                 : "+f"(c[0]), "+f"(c[1]), "+f"(c[2]), "+f"(c[3])
                 : "r"(a[0]), "r"(a[1]), "r"(a[2]), "r"(a[3]),
                   "r"(b[0]), "r"(b[1]));
}

// ---------------------------------------------------------------------------
// Scratch (device globals: allocation-free, graph-capture safe)
// ---------------------------------------------------------------------------
__device__ __align__(16) float g_q[B_ * H_ * T_ * DH_];    // (B,H,T,DH)
__device__ __align__(16) float g_k[B_ * H_ * T_ * DH_];
__device__ __align__(16) float g_v[B_ * H_ * T_ * DH_];
__device__ __align__(16) float g_attn[B_ * T_ * D_];       // (B,T,D)

__device__ __align__(16) __nv_bfloat16 g_xhi[M_ * D_];     // row-major [M][K]
__device__ __align__(16) __nv_bfloat16 g_xlo[M_ * D_];
__device__ __align__(16) __nv_bfloat16 g_ahi[M_ * D_];
__device__ __align__(16) __nv_bfloat16 g_alo[M_ * D_];
__device__ __align__(16) __nv_bfloat16 g_wT[4 * 2 * D_ * D_]; // [w][hi/lo][N][K]

// ---------------------------------------------------------------------------
// Pre-pass: elementwise fp32 -> bf16 hi/lo split (row-major, same layout)
// ---------------------------------------------------------------------------
__global__ __launch_bounds__(256) void split_kernel(const float* __restrict__ src,
                                                    __nv_bfloat16* __restrict__ hi,
                                                    __nv_bfloat16* __restrict__ lo) {
    const int i = (blockIdx.x * 256 + threadIdx.x) * 4;
    const float4 v = *(const float4*)&src[i];
    __nv_bfloat16 h[4], l[4];
    const float f[4] = {v.x, v.y, v.z, v.w};
#pragma unroll
    for (int j = 0; j < 4; j++) {
        h[j] = __float2bfloat16(f[j]);
        l[j] = __float2bfloat16(f[j] - __bfloat162float(h[j]));
    }
    *(uint2*)&hi[i] = *(const uint2*)h;
    *(uint2*)&lo[i] = *(const uint2*)l;
}

// ---------------------------------------------------------------------------
// Pre-pass: W[K][N] fp32 -> hiT/loT [N][K] bf16 (transpose + split)
// ---------------------------------------------------------------------------
__global__ __launch_bounds__(256) void tsplit_kernel(const float* __restrict__ W,
                                                     __nv_bfloat16* __restrict__ hiT,
                                                     __nv_bfloat16* __restrict__ loT) {
    __shared__ float t[32][33];
    const int tx = threadIdx.x & 31;
    const int ty = threadIdx.x >> 5;          // 0..7
    const int bn = blockIdx.x * 32;           // n tile
    const int bk = blockIdx.y * 32;           // k tile
#pragma unroll
    for (int i = 0; i < 4; i++)
        t[ty + 8 * i][tx] = W[(size_t)(bk + ty + 8 * i) * D_ + bn + tx];
    __syncthreads();
#pragma unroll
    for (int i = 0; i < 4; i++) {
        const int n = bn + ty + 8 * i;
        const float v = t[tx][ty + 8 * i];    // = W[bk+tx][n]
        const __nv_bfloat16 h = __float2bfloat16(v);
        const __nv_bfloat16 l = __float2bfloat16(v - __bfloat162float(h));
        hiT[(size_t)n * D_ + bk + tx] = h;
        loT[(size_t)n * D_ + bk + tx] = l;
    }
}

// ---------------------------------------------------------------------------
// HMMA GEMM: Y(4096x1024) = A @ W, fp32 via bf16 split (3 products).
// BM=128, BN=64, BK=64. 8 warps (4x2), warp tile 32x32.
// A smem [128][72] bf16 k-major, W smem [64][72] bf16 k-major ([N][K]).
// Padded stride 72 bf16 = 9 x 16B granules -> conflict-free ldmatrix.
// MODE 0: Y row-major (M,N).  MODE 1: Y scattered to (B,H,T,DH).
// ---------------------------------------------------------------------------
#define ASTR 72
#define GS_AHI 0
#define GS_ALO (128 * ASTR * 2)            // 18432
#define GS_WHI (2 * 128 * ASTR * 2)        // 36864
#define GS_WLO (GS_WHI + 64 * ASTR * 2)    // 46080
#define GS_TOT (GS_WLO + 64 * ASTR * 2)    // 55296

template <int MODE>
__global__ __launch_bounds__(256) void hmma_gemm(
    const __nv_bfloat16* __restrict__ Ahi, const __nv_bfloat16* __restrict__ Alo,
    const __nv_bfloat16* __restrict__ WhiT, const __nv_bfloat16* __restrict__ WloT,
    float* __restrict__ Y) {
    extern __shared__ __align__(16) char gsm[];
    __nv_bfloat16* sAhi = (__nv_bfloat16*)(gsm + GS_AHI);
    __nv_bfloat16* sAlo = (__nv_bfloat16*)(gsm + GS_ALO);
    __nv_bfloat16* sWhi = (__nv_bfloat16*)(gsm + GS_WHI);
    __nv_bfloat16* sWlo = (__nv_bfloat16*)(gsm + GS_WLO);

    const int tid  = threadIdx.x;
    const int wid  = tid >> 5;
    const int lane = tid & 31;
    const int m0 = blockIdx.y * 128;
    const int n0 = blockIdx.x * 64;
    const int wm = (wid >> 1) * 32;     // warp M origin (0,32,64,96)
    const int wn = (wid & 1) * 32;      // warp N origin (0,32)

    // ldmatrix per-lane addresses
    const u32 sbase = smem_u32(gsm);
    const int aRow = lane & 15;
    const int aK   = (lane >> 4) * 8;
    const int bN   = ((lane >> 4) << 3) | (lane & 7);
    const int bK   = ((lane >> 3) & 1) * 8;
    const u32 aHi0 = sbase + GS_AHI + ((wm + aRow) * ASTR + aK) * 2;
    const u32 aLo0 = sbase + GS_ALO + ((wm + aRow) * ASTR + aK) * 2;
    const u32 bHi0 = sbase + GS_WHI + ((wn + bN) * ASTR + bK) * 2;
    const u32 bLo0 = sbase + GS_WLO + ((wn + bN) * ASTR + bK) * 2;
    const u32 mtStep = 16 * ASTR * 2;   // +16 rows

    float acc[2][4][4];
#pragma unroll
    for (int mt = 0; mt < 2; mt++)
#pragma unroll
        for (int nt = 0; nt < 4; nt++)
#pragma unroll
            for (int r = 0; r < 4; r++) acc[mt][nt][r] = 0.f;

    for (int kt = 0; kt < 16; kt++) {
        const int kbase = kt * 64;
        // ---- stage A tiles (128x64 bf16, hi+lo): 1024 granules each, 4 iters
#pragma unroll
        for (int it = 0; it < 4; it++) {
            const int c = tid + it * 256;
            const int row = c >> 3;
            const int c8  = (c & 7) * 8;
            const size_t gi = (size_t)(m0 + row) * D_ + kbase + c8;
            *(uint4*)&sAhi[row * ASTR + c8] = *(const uint4*)&Ahi[gi];
            *(uint4*)&sAlo[row * ASTR + c8] = *(const uint4*)&Alo[gi];
        }
        // ---- stage W tiles (64x64 bf16, hi+lo): 512 granules each, 2 iters
#pragma unroll
        for (int it = 0; it < 2; it++) {
            const int c = tid + it * 256;
            const int row = c >> 3;
            const int c8  = (c & 7) * 8;
            const size_t gi = (size_t)(n0 + row) * D_ + kbase + c8;
            *(uint4*)&sWhi[row * ASTR + c8] = *(const uint4*)&WhiT[gi];
            *(uint4*)&sWlo[row * ASTR + c8] = *(const uint4*)&WloT[gi];
        }
        __syncthreads();

#pragma unroll
        for (int ks = 0; ks < 4; ks++) {
            const u32 ko = ks * 32;     // 16 bf16 per kstep
            u32 ah[2][4], al[2][4], bh[8], bl[8];
            ldsm4(ah[0][0], ah[0][1], ah[0][2], ah[0][3], aHi0 + ko);
            ldsm4(ah[1][0], ah[1][1], ah[1][2], ah[1][3], aHi0 + mtStep + ko);
            ldsm4(al[0][0], al[0][1], al[0][2], al[0][3], aLo0 + ko);
            ldsm4(al[1][0], al[1][1], al[1][2], al[1][3], aLo0 + mtStep + ko);
            ldsm4(bh[0], bh[1], bh[2], bh[3], bHi0 + ko);
            ldsm4(bh[4], bh[5], bh[6], bh[7], bHi0 + mtStep + ko);
            ldsm4(bl[0], bl[1], bl[2], bl[3], bLo0 + ko);
            ldsm4(bl[4], bl[5], bl[6], bl[7], bLo0 + mtStep + ko);
#pragma unroll
            for (int mt = 0; mt < 2; mt++)
#pragma unroll
                for (int nt = 0; nt < 4; nt++) {
                    mma16816(acc[mt][nt], ah[mt], &bh[nt * 2]);
                    mma16816(acc[mt][nt], ah[mt], &bl[nt * 2]);
                    mma16816(acc[mt][nt], al[mt], &bh[nt * 2]);
                }
        }
        __syncthreads();
    }

    // ---- epilogue
    const int r  = lane >> 2;
    const int cc = (lane & 3) * 2;
#pragma unroll
    for (int mt = 0; mt < 2; mt++) {
        const int mrow = m0 + wm + mt * 16 + r;
#pragma unroll
        for (int nt = 0; nt < 4; nt++) {
            const int ncol = wn + nt * 8 + cc;     // 0..63 within head / tile
            if (MODE == 0) {
                float* d0 = &Y[(size_t)mrow * 1024 + n0 + ncol];
                float* d1 = &Y[(size_t)(mrow + 8) * 1024 + n0 + ncol];
                *(float2*)d0 = make_float2(acc[mt][nt][0], acc[mt][nt][1]);
                *(float2*)d1 = make_float2(acc[mt][nt][2], acc[mt][nt][3]);
            } else {
                const int b = mrow >> 11;
                const int t = mrow & 2047;
                const int h = n0 >> 6;
                float* base = &Y[(((size_t)(b * H_ + h)) * T_ + t) * DH_ + ncol];
                *(float2*)base = make_float2(acc[mt][nt][0], acc[mt][nt][1]);
                *(float2*)(base + 8 * DH_) =
                    make_float2(acc[mt][nt][2], acc[mt][nt][3]);
            }
        }
    }
}

// ---------------------------------------------------------------------------
// Flash attention, fp32, f32x2 math (unchanged: ~96% of FFMA2 roofline)
// ---------------------------------------------------------------------------
#define BQ 128
#define BK 128
#define OFF_Q  0
#define OFF_K  8192
#define OFF_V  16384
#define OFF_P  25088
#define SMEM_FLOATS (25088 + 128 * 128)

__global__ __launch_bounds__(256) void attn_kernel(float* __restrict__ Yattn) {
    extern __shared__ __align__(16) float sm[];
    float* QsT = sm + OFF_Q;
    float* KsT = sm + OFF_K;
    float* Vs  = sm + OFF_V;
    float* PsT = sm + OFF_P;

    const int qb = gridDim.x - 1 - blockIdx.x;
    const int bh = blockIdx.y;
    const float* Q  = g_q + (size_t)bh * T_ * DH_ + (size_t)qb * BQ * DH_;
    const float* Kp = g_k + (size_t)bh * T_ * DH_;
    const float* Vp = g_v + (size_t)bh * T_ * DH_;

    const int tid = threadIdx.x;
    const int tx = tid & 15;
    const int ty = tid >> 4;

#pragma unroll
    for (int it = 0; it < 8; it++) {
        const int idx = tid + it * 256;
        const int row = idx >> 4;
        const int c4  = (idx & 15) * 4;
        const int pc  = row ^ ((idx & 7) << 2);
        const float4 v = *(const float4*)&Q[row * 64 + c4];
        QsT[(c4 + 0) * 128 + pc] = v.x;
        QsT[(c4 + 1) * 128 + pc] = v.y;
        QsT[(c4 + 2) * 128 + pc] = v.z;
        QsT[(c4 + 3) * 128 + pc] = v.w;
    }

    u64 o2[4][4];
    float mrow[8], lrow[8];
#pragma unroll
    for (int ip = 0; ip < 4; ip++)
#pragma unroll
        for (int j = 0; j < 4; j++) o2[ip][j] = 0ull;
#pragma unroll
    for (int i = 0; i < 8; i++) { mrow[i] = -1e30f; lrow[i] = 0.f; }

    for (int kb = 0; kb <= qb; kb++) {
        __syncthreads();
        const float* Kt = Kp + (size_t)kb * BK * DH_;
        const float* Vt = Vp + (size_t)kb * BK * DH_;
#pragma unroll
        for (int it = 0; it < 8; it++) {
            const int idx = tid + it * 256;
            const int row = idx >> 4;
            const int c4  = (idx & 15) * 4;
            const int pc  = row ^ ((idx & 7) << 2);
            const float4 kv = *(const float4*)&Kt[row * 64 + c4];
            KsT[(c4 + 0) * 128 + pc] = kv.x;
            KsT[(c4 + 1) * 128 + pc] = kv.y;
            KsT[(c4 + 2) * 128 + pc] = kv.z;
            KsT[(c4 + 3) * 128 + pc] = kv.w;
            const float4 vv = *(const float4*)&Vt[row * 64 + c4];
            *(float4*)&Vs[row * 68 + c4] = vv;
        }
        __syncthreads();

        u64 s2[8][4];
#pragma unroll
        for (int i = 0; i < 8; i++)
#pragma unroll
            for (int jp = 0; jp < 4; jp++) s2[i][jp] = 0ull;

#pragma unroll 4
        for (int k = 0; k < 64; k++) {
            const int swk = ((k >> 2) & 7) << 2;
            const float4 q0 = *(const float4*)&QsT[k * 128 + ((ty * 8) ^ swk)];
            const float4 q1 = *(const float4*)&QsT[k * 128 + ((ty * 8 + 4) ^ swk)];
            const ulonglong2 k0 = *(const ulonglong2*)&KsT[k * 128 + ((tx * 8) ^ swk)];
            const ulonglong2 k1 = *(const ulonglong2*)&KsT[k * 128 + ((tx * 8 + 4) ^ swk)];
            const u64 kd[4] = {k0.x, k0.y, k1.x, k1.y};
            const float qa[8] = {q0.x, q0.y, q0.z, q0.w, q1.x, q1.y, q1.z, q1.w};
#pragma unroll
            for (int i = 0; i < 8; i++) {
                const u64 qd = pk1(qa[i]);
#pragma unroll
                for (int jp = 0; jp < 4; jp++) fma2(s2[i][jp], qd, kd[jp]);
            }
        }

        float s[8][8];
#pragma unroll
        for (int i = 0; i < 8; i++)
#pragma unroll
            for (int jp = 0; jp < 4; jp++) {
                const float2 f = upk(s2[i][jp]);
                s[i][2 * jp]     = f.x;
                s[i][2 * jp + 1] = f.y;
            }

        const bool diag = (kb == qb);
        float alpha[8];
#pragma unroll
        for (int i = 0; i < 8; i++) {
            const int qrow = ty * 8 + i;
            float rmax = -1e30f;
#pragma unroll
            for (int j = 0; j < 8; j++) {
                float v = s[i][j] * 0.125f;
                if (diag && (tx * 8 + j) > qrow) v = -1e30f;
                s[i][j] = v;
                rmax = fmaxf(rmax, v);
            }
#pragma unroll
            for (int off = 8; off >= 1; off >>= 1)
                rmax = fmaxf(rmax, __shfl_xor_sync(0xffffffffu, rmax, off));

            const float mnew = fmaxf(mrow[i], rmax);
            alpha[i] = __expf(mrow[i] - mnew);
            float rsum = 0.f;
#pragma unroll
            for (int j = 0; j < 8; j++) {
                const float p = __expf(s[i][j] - mnew);
                s[i][j] = p;
                rsum += p;
            }
#pragma unroll
            for (int off = 8; off >= 1; off >>= 1)
                rsum += __shfl_xor_sync(0xffffffffu, rsum, off);

            lrow[i] = lrow[i] * alpha[i] + rsum;
            mrow[i] = mnew;
        }
#pragma unroll
        for (int ip = 0; ip < 4; ip++) {
            const u64 al2 = pk2(alpha[2 * ip], alpha[2 * ip + 1]);
#pragma unroll
            for (int j = 0; j < 4; j++) o2[ip][j] = mul2(o2[ip][j], al2);
        }

        {
            const int swp = (tx & 7) << 2;
#pragma unroll
            for (int j = 0; j < 8; j++) {
                float4 w0 = make_float4(s[0][j], s[1][j], s[2][j], s[3][j]);
                float4 w1 = make_float4(s[4][j], s[5][j], s[6][j], s[7][j]);
                *(float4*)&PsT[(tx * 8 + j) * 128 + ((ty * 8) ^ swp)]     = w0;
                *(float4*)&PsT[(tx * 8 + j) * 128 + ((ty * 8 + 4) ^ swp)] = w1;
            }
        }
        __syncthreads();

#pragma unroll 4
        for (int kk = 0; kk < 128; kk++) {
            const int swp = ((kk >> 3) & 7) << 2;
            const ulonglong2 p01 = *(const ulonglong2*)&PsT[kk * 128 + ((ty * 8) ^ swp)];
            const ulonglong2 p23 = *(const ulonglong2*)&PsT[kk * 128 + ((ty * 8 + 4) ^ swp)];
            const u64 pd[4] = {p01.x, p01.y, p23.x, p23.y};
            const float4 vv = *(const float4*)&Vs[kk * 68 + tx * 4];
            const u64 vd[4] = {pk1(vv.x), pk1(vv.y), pk1(vv.z), pk1(vv.w)};
#pragma unroll
            for (int ip = 0; ip < 4; ip++)
#pragma unroll
                for (int j = 0; j < 4; j++) fma2(o2[ip][j], pd[ip], vd[j]);
        }
    }

    const int b = bh >> 4;
    const int h = bh & 15;
#pragma unroll
    for (int ip = 0; ip < 4; ip++) {
        const u64 li = pk2(1.f / lrow[2 * ip], 1.f / lrow[2 * ip + 1]);
        float2 c0 = upk(mul2(o2[ip][0], li));
        float2 c1 = upk(mul2(o2[ip][1], li));
        float2 c2 = upk(mul2(o2[ip][2], li));
        float2 c3 = upk(mul2(o2[ip][3], li));
        const int t0 = qb * BQ + ty * 8 + 2 * ip;
        float* base0 = &Yattn[((size_t)(b * T_ + t0)) * D_ + h * DH_ + tx * 4];
        float* base1 = &Yattn[((size_t)(b * T_ + t0 + 1)) * D_ + h * DH_ + tx * 4];
        *(float4*)base0 = make_float4(c0.x, c1.x, c2.x, c3.x);
        *(float4*)base1 = make_float4(c0.y, c1.y, c2.y, c3.y);
    }
}

// ---------------------------------------------------------------------------
// Host launcher (graph-capturable)
// ---------------------------------------------------------------------------
extern "C" void kernel_launch(void* const* d_in, const int* in_sizes, int n_in,
                              void* d_out, int out_size) {
    (void)in_sizes; (void)n_in; (void)out_size;
    const float* x  = (const float*)d_in[0];
    const float* W[4] = {(const float*)d_in[1], (const float*)d_in[2],
                         (const float*)d_in[3], (const float*)d_in[4]};
    float* out = (float*)d_out;

    float *q, *k, *v, *attn;
    __nv_bfloat16 *xhi, *xlo, *ahi, *alo, *wT;
    cudaGetSymbolAddress((void**)&q,    g_q);
    cudaGetSymbolAddress((void**)&k,    g_k);
    cudaGetSymbolAddress((void**)&v,    g_v);
    cudaGetSymbolAddress((void**)&attn, g_attn);
    cudaGetSymbolAddress((void**)&xhi,  g_xhi);
    cudaGetSymbolAddress((void**)&xlo,  g_xlo);
    cudaGetSymbolAddress((void**)&ahi,  g_ahi);
    cudaGetSymbolAddress((void**)&alo,  g_alo);
    cudaGetSymbolAddress((void**)&wT,   g_wT);

    cudaFuncSetAttribute(hmma_gemm<0>,
                         cudaFuncAttributeMaxDynamicSharedMemorySize, GS_TOT);
    cudaFuncSetAttribute(hmma_gemm<1>,
                         cudaFuncAttributeMaxDynamicSharedMemorySize, GS_TOT);
    const int asmem = SMEM_FLOATS * (int)sizeof(float);
    cudaFuncSetAttribute(attn_kernel,
                         cudaFuncAttributeMaxDynamicSharedMemorySize, asmem);

    // --- pre-pass: splits ---
    split_kernel<<<M_ * D_ / 1024, 256>>>(x, xhi, xlo);
    const dim3 tgrid(D_ / 32, D_ / 32);
    for (int w = 0; w < 4; w++)
        tsplit_kernel<<<tgrid, 256>>>(W[w],
                                      wT + (size_t)(2 * w)     * D_ * D_,
                                      wT + (size_t)(2 * w + 1) * D_ * D_);

    // --- projections (HMMA tensor cores) ---
    const dim3 ggrid(D_ / 64, M_ / 128);   // (16, 32)
    hmma_gemm<1><<<ggrid, 256, GS_TOT>>>(xhi, xlo,
        wT + 0 * (size_t)D_ * D_, wT + 1 * (size_t)D_ * D_, q);
    hmma_gemm<1><<<ggrid, 256, GS_TOT>>>(xhi, xlo,
        wT + 2 * (size_t)D_ * D_, wT + 3 * (size_t)D_ * D_, k);
    hmma_gemm<1><<<ggrid, 256, GS_TOT>>>(xhi, xlo,
        wT + 4 * (size_t)D_ * D_, wT + 5 * (size_t)D_ * D_, v);

    // --- attention ---
    const dim3 agrid(T_ / BQ, B_ * H_);    // (16, 32)
    attn_kernel<<<agrid, 256, asmem>>>(attn);

    // --- output projection ---
    split_kernel<<<M_ * D_ / 1024, 256>>>(attn, ahi, alo);
    hmma_gemm<0><<<ggrid, 256, GS_TOT>>>(ahi, alo,
        wT + 6 * (size_t)D_ * D_, wT + 7 * (size_t)D_ * D_, out);
}

// round 11
// speedup vs baseline: 3.1437x; 1.5345x over previous
#include <cuda_runtime.h>
#include <cuda_bf16.h>
#include <cstdint>
#include <math.h>

#define B_  2
#define T_  2048
#define D_  1024
#define H_  16
#define DH_ 64
#define M_  (B_ * T_)
#define BH_ (B_ * H_)

typedef unsigned long long u64;
typedef unsigned int u32;
typedef __nv_bfloat16 bf16;

// ---------------------------------------------------------------------------
// Generic tensor-core PTX (sm_80+, legal under compute_103 virtual target)
// ---------------------------------------------------------------------------
__device__ __forceinline__ u32 smem_u32(const void* p) {
    u32 a;
    asm("{ .reg .u64 t; cvta.to.shared.u64 t, %1; cvt.u32.u64 %0, t; }"
        : "=r"(a) : "l"(p));
    return a;
}
__device__ __forceinline__ void ldsm4(u32& r0, u32& r1, u32& r2, u32& r3, u32 addr) {
    asm volatile("ldmatrix.sync.aligned.m8n8.x4.shared.b16 {%0,%1,%2,%3}, [%4];"
                 : "=r"(r0), "=r"(r1), "=r"(r2), "=r"(r3) : "r"(addr));
}
__device__ __forceinline__ void mma16816(float* c, const u32* a, const u32* b) {
    asm volatile("mma.sync.aligned.m16n8k16.row.col.f32.bf16.bf16.f32 "
                 "{%0,%1,%2,%3}, {%4,%5,%6,%7}, {%8,%9}, {%0,%1,%2,%3};"
                 : "+f"(c[0]), "+f"(c[1]), "+f"(c[2]), "+f"(c[3])
                 : "r"(a[0]), "r"(a[1]), "r"(a[2]), "r"(a[3]),
                   "r"(b[0]), "r"(b[1]));
}
// pack two f32 -> bf16x2 (lo = a, hi = b) and its hi/lo split companion
__device__ __forceinline__ u32 pkbf(float a, float b) {
    __nv_bfloat162 h = __float22bfloat162_rn(make_float2(a, b));
    return *(u32*)&h;
}
__device__ __forceinline__ void split2(float a, float b, u32& hi, u32& lo) {
    __nv_bfloat162 h = __float22bfloat162_rn(make_float2(a, b));
    float2 hf = __bfloat1622float2(h);
    __nv_bfloat162 l = __float22bfloat162_rn(make_float2(a - hf.x, b - hf.y));
    hi = *(u32*)&h;
    lo = *(u32*)&l;
}

// ---------------------------------------------------------------------------
// Scratch (device globals: allocation-free, graph-capture safe)
// ---------------------------------------------------------------------------
__device__ __align__(16) bf16 g_xhi[M_ * D_];
__device__ __align__(16) bf16 g_xlo[M_ * D_];
__device__ __align__(16) bf16 g_wT[4 * 2 * D_ * D_];        // [w][hi/lo][N][K]
__device__ __align__(16) bf16 g_qhi[BH_ * T_ * DH_];        // (B,H,T,DH)
__device__ __align__(16) bf16 g_qlo[BH_ * T_ * DH_];
__device__ __align__(16) bf16 g_khi[BH_ * T_ * DH_];
__device__ __align__(16) bf16 g_klo[BH_ * T_ * DH_];
__device__ __align__(16) bf16 g_vthi[BH_ * DH_ * T_];       // (B,H,DH,T)  V^T
__device__ __align__(16) bf16 g_vtlo[BH_ * DH_ * T_];
__device__ __align__(16) bf16 g_ahi[M_ * D_];               // attn out hi/lo
__device__ __align__(16) bf16 g_alo[M_ * D_];

// ---------------------------------------------------------------------------
// Pre-pass: fp32 -> bf16 hi/lo split (row-major)
// ---------------------------------------------------------------------------
__global__ __launch_bounds__(256) void split_kernel(const float* __restrict__ src,
                                                    bf16* __restrict__ hi,
                                                    bf16* __restrict__ lo) {
    const int i = (blockIdx.x * 256 + threadIdx.x) * 4;
    const float4 v = *(const float4*)&src[i];
    bf16 h[4], l[4];
    const float f[4] = {v.x, v.y, v.z, v.w};
#pragma unroll
    for (int j = 0; j < 4; j++) {
        h[j] = __float2bfloat16(f[j]);
        l[j] = __float2bfloat16(f[j] - __bfloat162float(h[j]));
    }
    *(uint2*)&hi[i] = *(const uint2*)h;
    *(uint2*)&lo[i] = *(const uint2*)l;
}

// ---------------------------------------------------------------------------
// Pre-pass: W[K][N] fp32 -> hiT/loT [N][K] bf16 (transpose + split)
// ---------------------------------------------------------------------------
__global__ __launch_bounds__(256) void tsplit_kernel(const float* __restrict__ W,
                                                     bf16* __restrict__ hiT,
                                                     bf16* __restrict__ loT) {
    __shared__ float t[32][33];
    const int tx = threadIdx.x & 31;
    const int ty = threadIdx.x >> 5;
    const int bn = blockIdx.x * 32;
    const int bk = blockIdx.y * 32;
#pragma unroll
    for (int i = 0; i < 4; i++)
        t[ty + 8 * i][tx] = W[(size_t)(bk + ty + 8 * i) * D_ + bn + tx];
    __syncthreads();
#pragma unroll
    for (int i = 0; i < 4; i++) {
        const int n = bn + ty + 8 * i;
        const float v = t[tx][ty + 8 * i];
        const bf16 h = __float2bfloat16(v);
        const bf16 l = __float2bfloat16(v - __bfloat162float(h));
        hiT[(size_t)n * D_ + bk + tx] = h;
        loT[(size_t)n * D_ + bk + tx] = l;
    }
}

// ---------------------------------------------------------------------------
// HMMA GEMM (validated R10 core). MODE 0: f32 row-major out.
// MODE 1: bf16 hi/lo pair to (B,H,T,DH).  MODE 2: bf16 hi/lo pair to V^T.
// ---------------------------------------------------------------------------
#define ASTR 72
#define GS_AHI 0
#define GS_ALO (128 * ASTR * 2)
#define GS_WHI (2 * 128 * ASTR * 2)
#define GS_WLO (GS_WHI + 64 * ASTR * 2)
#define GS_TOT (GS_WLO + 64 * ASTR * 2)

template <int MODE>
__global__ __launch_bounds__(256) void hmma_gemm(
    const bf16* __restrict__ Ahi, const bf16* __restrict__ Alo,
    const bf16* __restrict__ WhiT, const bf16* __restrict__ WloT,
    void* __restrict__ Y0, void* __restrict__ Y1) {
    extern __shared__ __align__(16) char gsm[];
    bf16* sAhi = (bf16*)(gsm + GS_AHI);
    bf16* sAlo = (bf16*)(gsm + GS_ALO);
    bf16* sWhi = (bf16*)(gsm + GS_WHI);
    bf16* sWlo = (bf16*)(gsm + GS_WLO);

    const int tid  = threadIdx.x;
    const int wid  = tid >> 5;
    const int lane = tid & 31;
    const int m0 = blockIdx.y * 128;
    const int n0 = blockIdx.x * 64;
    const int wm = (wid >> 1) * 32;
    const int wn = (wid & 1) * 32;

    const u32 sbase = smem_u32(gsm);
    const int aRow = lane & 15;
    const int aK   = (lane >> 4) * 8;
    const int bN   = ((lane >> 4) << 3) | (lane & 7);
    const int bK   = ((lane >> 3) & 1) * 8;
    const u32 aHi0 = sbase + GS_AHI + ((wm + aRow) * ASTR + aK) * 2;
    const u32 aLo0 = sbase + GS_ALO + ((wm + aRow) * ASTR + aK) * 2;
    const u32 bHi0 = sbase + GS_WHI + ((wn + bN) * ASTR + bK) * 2;
    const u32 bLo0 = sbase + GS_WLO + ((wn + bN) * ASTR + bK) * 2;
    const u32 mtStep = 16 * ASTR * 2;

    float acc[2][4][4];
#pragma unroll
    for (int mt = 0; mt < 2; mt++)
#pragma unroll
        for (int nt = 0; nt < 4; nt++)
#pragma unroll
            for (int r = 0; r < 4; r++) acc[mt][nt][r] = 0.f;

    for (int kt = 0; kt < 16; kt++) {
        const int kbase = kt * 64;
#pragma unroll
        for (int it = 0; it < 4; it++) {
            const int c = tid + it * 256;
            const int row = c >> 3;
            const int c8  = (c & 7) * 8;
            const size_t gi = (size_t)(m0 + row) * D_ + kbase + c8;
            *(uint4*)&sAhi[row * ASTR + c8] = *(const uint4*)&Ahi[gi];
            *(uint4*)&sAlo[row * ASTR + c8] = *(const uint4*)&Alo[gi];
        }
#pragma unroll
        for (int it = 0; it < 2; it++) {
            const int c = tid + it * 256;
            const int row = c >> 3;
            const int c8  = (c & 7) * 8;
            const size_t gi = (size_t)(n0 + row) * D_ + kbase + c8;
            *(uint4*)&sWhi[row * ASTR + c8] = *(const uint4*)&WhiT[gi];
            *(uint4*)&sWlo[row * ASTR + c8] = *(const uint4*)&WloT[gi];
        }
        __syncthreads();

#pragma unroll
        for (int ks = 0; ks < 4; ks++) {
            const u32 ko = ks * 32;
            u32 ah[2][4], al[2][4], bh[8], bl[8];
            ldsm4(ah[0][0], ah[0][1], ah[0][2], ah[0][3], aHi0 + ko);
            ldsm4(ah[1][0], ah[1][1], ah[1][2], ah[1][3], aHi0 + mtStep + ko);
            ldsm4(al[0][0], al[0][1], al[0][2], al[0][3], aLo0 + ko);
            ldsm4(al[1][0], al[1][1], al[1][2], al[1][3], aLo0 + mtStep + ko);
            ldsm4(bh[0], bh[1], bh[2], bh[3], bHi0 + ko);
            ldsm4(bh[4], bh[5], bh[6], bh[7], bHi0 + mtStep + ko);
            ldsm4(bl[0], bl[1], bl[2], bl[3], bLo0 + ko);
            ldsm4(bl[4], bl[5], bl[6], bl[7], bLo0 + mtStep + ko);
#pragma unroll
            for (int mt = 0; mt < 2; mt++)
#pragma unroll
                for (int nt = 0; nt < 4; nt++) {
                    mma16816(acc[mt][nt], ah[mt], &bh[nt * 2]);
                    mma16816(acc[mt][nt], ah[mt], &bl[nt * 2]);
                    mma16816(acc[mt][nt], al[mt], &bh[nt * 2]);
                }
        }
        __syncthreads();
    }

    const int r  = lane >> 2;
    const int cc = (lane & 3) * 2;
#pragma unroll
    for (int mt = 0; mt < 2; mt++) {
        const int mrow = m0 + wm + mt * 16 + r;
        const int b = mrow >> 11;
        const int t = mrow & 2047;
        const int h = n0 >> 6;
#pragma unroll
        for (int nt = 0; nt < 4; nt++) {
            const int ncol = wn + nt * 8 + cc;
            const float a0 = acc[mt][nt][0], a1 = acc[mt][nt][1];
            const float a2 = acc[mt][nt][2], a3 = acc[mt][nt][3];
            if (MODE == 0) {
                float* Y = (float*)Y0;
                *(float2*)&Y[(size_t)mrow * 1024 + n0 + ncol] = make_float2(a0, a1);
                *(float2*)&Y[(size_t)(mrow + 8) * 1024 + n0 + ncol] = make_float2(a2, a3);
            } else if (MODE == 1) {
                bf16* hi = (bf16*)Y0; bf16* lo = (bf16*)Y1;
                const size_t base = ((size_t)((b * H_ + h) * T_ + t)) * DH_ + ncol;
                u32 h01, l01, h23, l23;
                split2(a0, a1, h01, l01);
                split2(a2, a3, h23, l23);
                *(u32*)&hi[base] = h01;
                *(u32*)&lo[base] = l01;
                *(u32*)&hi[base + 8 * DH_] = h23;
                *(u32*)&lo[base + 8 * DH_] = l23;
            } else {
                bf16* hi = (bf16*)Y0; bf16* lo = (bf16*)Y1;
                const size_t r0b = ((size_t)((b * H_ + h) * DH_ + ncol)) * T_;
                const size_t r1b = r0b + T_;   // ncol+1
                const float f[4] = {a0, a1, a2, a3};
                const size_t ix[4] = {r0b + t, r1b + t, r0b + t + 8, r1b + t + 8};
#pragma unroll
                for (int e = 0; e < 4; e++) {
                    const bf16 hv = __float2bfloat16(f[e]);
                    hi[ix[e]] = hv;
                    lo[ix[e]] = __float2bfloat16(f[e] - __bfloat162float(hv));
                }
            }
        }
    }
}

// ---------------------------------------------------------------------------
// HMMA flash attention. CTA = (bh, 128 q-rows), 8 warps x 16 q-rows.
// 3-product bf16 split for S and PV; P fragments built in registers.
// Writes bf16 hi/lo attn output (feeds the O projection directly).
// ---------------------------------------------------------------------------
#define QSTR 72         // bf16 stride for Q/K tiles (rows of 64)
#define VSTR 136        // bf16 stride for VT tiles (rows of 128)
#define AQHI 0
#define AQLO 18432
#define AKHI 36864
#define AKLO 55296
#define AVHI 73728
#define AVLO 91136
#define ATT_SMEM 108544

__global__ __launch_bounds__(256, 1) void attn_hmma(
    const bf16* __restrict__ Qhi, const bf16* __restrict__ Qlo,
    const bf16* __restrict__ Khi, const bf16* __restrict__ Klo,
    const bf16* __restrict__ VThi, const bf16* __restrict__ VTlo,
    bf16* __restrict__ Ohi, bf16* __restrict__ Olo) {
    extern __shared__ __align__(16) char smc[];
    const u32 sb = smem_u32(smc);

    const int qb = gridDim.x - 1 - blockIdx.x;   // heavy blocks first
    const int bh = blockIdx.y;
    const int tid  = threadIdx.x;
    const int wid  = tid >> 5;
    const int lane = tid & 31;
    const int wq = wid * 16;

    // ---- stage Q (128 x 64 hi/lo)
    const bf16* Qg0 = Qhi + ((size_t)bh * T_ + qb * 128) * DH_;
    const bf16* Qg1 = Qlo + ((size_t)bh * T_ + qb * 128) * DH_;
#pragma unroll
    for (int it = 0; it < 4; it++) {
        const int c = tid + it * 256;
        const int row = c >> 3;
        const int k8  = (c & 7) * 8;
        *(uint4*)(smc + AQHI + (row * QSTR + k8) * 2) = *(const uint4*)&Qg0[row * 64 + k8];
        *(uint4*)(smc + AQLO + (row * QSTR + k8) * 2) = *(const uint4*)&Qg1[row * 64 + k8];
    }
    __syncthreads();

    // ---- extract Q fragments (resident in registers)
    const int aRow = lane & 15;
    const int aK   = (lane >> 4) * 8;
    const u32 qa = sb + AQHI + ((wq + aRow) * QSTR + aK) * 2;
    u32 qf[2][4][4];
#pragma unroll
    for (int ks = 0; ks < 4; ks++) {
        ldsm4(qf[0][ks][0], qf[0][ks][1], qf[0][ks][2], qf[0][ks][3], qa + ks * 32);
        ldsm4(qf[1][ks][0], qf[1][ks][1], qf[1][ks][2], qf[1][ks][3],
              qa + (AQLO - AQHI) + ks * 32);
    }

    float oacc[8][4];
#pragma unroll
    for (int nt = 0; nt < 8; nt++)
#pragma unroll
        for (int r = 0; r < 4; r++) oacc[nt][r] = 0.f;
    float mrw[2] = {-1e30f, -1e30f}, lrw[2] = {0.f, 0.f};

    const bf16* Kg0 = Khi + (size_t)bh * T_ * DH_;
    const bf16* Kg1 = Klo + (size_t)bh * T_ * DH_;
    const bf16* Vg0 = VThi + (size_t)bh * DH_ * T_;
    const bf16* Vg1 = VTlo + (size_t)bh * DH_ * T_;

    const int bN = ((lane >> 4) << 3) | (lane & 7);
    const int bK = ((lane >> 3) & 1) * 8;
    const u32 kba = sb + AKHI + (bN * QSTR + bK) * 2;
    const u32 vba = sb + AVHI + (bN * VSTR + bK) * 2;
    const int r0 = lane >> 2;
    const int cb = (lane & 3) * 2;

    for (int kb = 0; kb <= qb; kb++) {
        __syncthreads();   // prior iteration's ldsm reads done
        // ---- stage K (128x64 hi/lo) and VT (64x128 hi/lo)
#pragma unroll
        for (int it = 0; it < 4; it++) {
            const int c = tid + it * 256;
            const int row = c >> 3;
            const int k8  = (c & 7) * 8;
            const size_t gi = (size_t)(kb * 128 + row) * 64 + k8;
            *(uint4*)(smc + AKHI + (row * QSTR + k8) * 2) = *(const uint4*)&Kg0[gi];
            *(uint4*)(smc + AKLO + (row * QSTR + k8) * 2) = *(const uint4*)&Kg1[gi];
        }
#pragma unroll
        for (int it = 0; it < 4; it++) {
            const int c = tid + it * 256;
            const int row = c >> 4;
            const int k8  = (c & 15) * 8;
            const size_t gi = (size_t)row * T_ + kb * 128 + k8;
            *(uint4*)(smc + AVHI + (row * VSTR + k8) * 2) = *(const uint4*)&Vg0[gi];
            *(uint4*)(smc + AVLO + (row * VSTR + k8) * 2) = *(const uint4*)&Vg1[gi];
        }
        __syncthreads();

        // ---- S = Q @ K^T (3-product split)
        float sacc[16][4];
#pragma unroll
        for (int nt = 0; nt < 16; nt++)
#pragma unroll
            for (int r = 0; r < 4; r++) sacc[nt][r] = 0.f;

#pragma unroll
        for (int nc = 0; nc < 8; nc++) {
            const u32 nco = (u32)(nc * 16 * QSTR * 2);
#pragma unroll
            for (int ks = 0; ks < 4; ks++) {
                u32 kh[4], kl[4];
                ldsm4(kh[0], kh[1], kh[2], kh[3], kba + nco + ks * 32);
                ldsm4(kl[0], kl[1], kl[2], kl[3],
                      kba + (AKLO - AKHI) + nco + ks * 32);
                mma16816(sacc[2 * nc],     qf[0][ks], &kh[0]);
                mma16816(sacc[2 * nc],     qf[0][ks], &kl[0]);
                mma16816(sacc[2 * nc],     qf[1][ks], &kh[0]);
                mma16816(sacc[2 * nc + 1], qf[0][ks], &kh[2]);
                mma16816(sacc[2 * nc + 1], qf[0][ks], &kl[2]);
                mma16816(sacc[2 * nc + 1], qf[1][ks], &kh[2]);
            }
        }

        // ---- scale + mask + online softmax (rows r0 and r0+8, 4-lane groups)
        const bool diag = (kb == qb);
        float alpha[2];
#pragma unroll
        for (int rh = 0; rh < 2; rh++) {
            const int rl = wq + r0 + rh * 8;
            float mx = -1e30f;
#pragma unroll
            for (int nt = 0; nt < 16; nt++) {
                float v0 = sacc[nt][2 * rh]     * 0.125f;
                float v1 = sacc[nt][2 * rh + 1] * 0.125f;
                if (diag) {
                    const int col = nt * 8 + cb;
                    if (col > rl)     v0 = -1e30f;
                    if (col + 1 > rl) v1 = -1e30f;
                }
                sacc[nt][2 * rh]     = v0;
                sacc[nt][2 * rh + 1] = v1;
                mx = fmaxf(mx, fmaxf(v0, v1));
            }
            mx = fmaxf(mx, __shfl_xor_sync(0xffffffffu, mx, 1));
            mx = fmaxf(mx, __shfl_xor_sync(0xffffffffu, mx, 2));
            const float mnew = fmaxf(mrw[rh], mx);
            alpha[rh] = __expf(mrw[rh] - mnew);
            float rs = 0.f;
#pragma unroll
            for (int nt = 0; nt < 16; nt++) {
                const float p0 = __expf(sacc[nt][2 * rh]     - mnew);
                const float p1 = __expf(sacc[nt][2 * rh + 1] - mnew);
                sacc[nt][2 * rh]     = p0;
                sacc[nt][2 * rh + 1] = p1;
                rs += p0 + p1;
            }
            rs += __shfl_xor_sync(0xffffffffu, rs, 1);
            rs += __shfl_xor_sync(0xffffffffu, rs, 2);
            lrw[rh] = lrw[rh] * alpha[rh] + rs;
            mrw[rh] = mnew;
        }
#pragma unroll
        for (int nt = 0; nt < 8; nt++) {
            oacc[nt][0] *= alpha[0];
            oacc[nt][1] *= alpha[0];
            oacc[nt][2] *= alpha[1];
            oacc[nt][3] *= alpha[1];
        }

        // ---- O += P @ V (P fragments from registers, 3-product split)
#pragma unroll
        for (int ks = 0; ks < 8; ks++) {
            u32 ph[4], pl[4];
            split2(sacc[2 * ks][0],     sacc[2 * ks][1],     ph[0], pl[0]);
            split2(sacc[2 * ks][2],     sacc[2 * ks][3],     ph[1], pl[1]);
            split2(sacc[2 * ks + 1][0], sacc[2 * ks + 1][1], ph[2], pl[2]);
            split2(sacc[2 * ks + 1][2], sacc[2 * ks + 1][3], ph[3], pl[3]);
#pragma unroll
            for (int nc = 0; nc < 4; nc++) {
                const u32 nco = (u32)(nc * 16 * VSTR * 2);
                u32 vh[4], vl[4];
                ldsm4(vh[0], vh[1], vh[2], vh[3], vba + nco + ks * 32);
                ldsm4(vl[0], vl[1], vl[2], vl[3],
                      vba + (AVLO - AVHI) + nco + ks * 32);
                mma16816(oacc[2 * nc],     ph, &vh[0]);
                mma16816(oacc[2 * nc],     ph, &vl[0]);
                mma16816(oacc[2 * nc],     pl, &vh[0]);
                mma16816(oacc[2 * nc + 1], ph, &vh[2]);
                mma16816(oacc[2 * nc + 1], ph, &vl[2]);
                mma16816(oacc[2 * nc + 1], pl, &vh[2]);
            }
        }
    }

    // ---- normalize + bf16 hi/lo write to (B,T,D)
    const float inv0 = 1.f / lrw[0];
    const float inv1 = 1.f / lrw[1];
    const int b  = bh >> 4;
    const int hh = bh & 15;
    const int t0 = qb * 128 + wq + r0;
#pragma unroll
    for (int nt = 0; nt < 8; nt++) {
        const int col = hh * 64 + nt * 8 + cb;
        u32 h01, l01, h23, l23;
        split2(oacc[nt][0] * inv0, oacc[nt][1] * inv0, h01, l01);
        split2(oacc[nt][2] * inv1, oacc[nt][3] * inv1, h23, l23);
        const size_t i0 = ((size_t)(b * T_ + t0)) * D_ + col;
        const size_t i1 = ((size_t)(b * T_ + t0 + 8)) * D_ + col;
        *(u32*)&Ohi[i0] = h01;
        *(u32*)&Olo[i0] = l01;
        *(u32*)&Ohi[i1] = h23;
        *(u32*)&Olo[i1] = l23;
    }
}

// ---------------------------------------------------------------------------
// Host launcher (graph-capturable)
// ---------------------------------------------------------------------------
extern "C" void kernel_launch(void* const* d_in, const int* in_sizes, int n_in,
                              void* d_out, int out_size) {
    (void)in_sizes; (void)n_in; (void)out_size;
    const float* x = (const float*)d_in[0];
    const float* W[4] = {(const float*)d_in[1], (const float*)d_in[2],
                         (const float*)d_in[3], (const float*)d_in[4]};
    float* out = (float*)d_out;

    bf16 *xhi, *xlo, *wT, *qhi, *qlo, *khi, *klo, *vthi, *vtlo, *ahi, *alo;
    cudaGetSymbolAddress((void**)&xhi,  g_xhi);
    cudaGetSymbolAddress((void**)&xlo,  g_xlo);
    cudaGetSymbolAddress((void**)&wT,   g_wT);
    cudaGetSymbolAddress((void**)&qhi,  g_qhi);
    cudaGetSymbolAddress((void**)&qlo,  g_qlo);
    cudaGetSymbolAddress((void**)&khi,  g_khi);
    cudaGetSymbolAddress((void**)&klo,  g_klo);
    cudaGetSymbolAddress((void**)&vthi, g_vthi);
    cudaGetSymbolAddress((void**)&vtlo, g_vtlo);
    cudaGetSymbolAddress((void**)&ahi,  g_ahi);
    cudaGetSymbolAddress((void**)&alo,  g_alo);

    cudaFuncSetAttribute(hmma_gemm<0>, cudaFuncAttributeMaxDynamicSharedMemorySize, GS_TOT);
    cudaFuncSetAttribute(hmma_gemm<1>, cudaFuncAttributeMaxDynamicSharedMemorySize, GS_TOT);
    cudaFuncSetAttribute(hmma_gemm<2>, cudaFuncAttributeMaxDynamicSharedMemorySize, GS_TOT);
    cudaFuncSetAttribute(attn_hmma, cudaFuncAttributeMaxDynamicSharedMemorySize, ATT_SMEM);

    // --- pre-pass ---
    split_kernel<<<M_ * D_ / 1024, 256>>>(x, xhi, xlo);
    const dim3 tgrid(D_ / 32, D_ / 32);
    for (int w = 0; w < 4; w++)
        tsplit_kernel<<<tgrid, 256>>>(W[w],
                                      wT + (size_t)(2 * w)     * D_ * D_,
                                      wT + (size_t)(2 * w + 1) * D_ * D_);

    // --- projections: write bf16 hi/lo directly (Q,K head-major; V transposed) ---
    const dim3 ggrid(D_ / 64, M_ / 128);
    hmma_gemm<1><<<ggrid, 256, GS_TOT>>>(xhi, xlo,
        wT + 0 * (size_t)D_ * D_, wT + 1 * (size_t)D_ * D_, qhi, qlo);
    hmma_gemm<1><<<ggrid, 256, GS_TOT>>>(xhi, xlo,
        wT + 2 * (size_t)D_ * D_, wT + 3 * (size_t)D_ * D_, khi, klo);
    hmma_gemm<2><<<ggrid, 256, GS_TOT>>>(xhi, xlo,
        wT + 4 * (size_t)D_ * D_, wT + 5 * (size_t)D_ * D_, vthi, vtlo);

    // --- attention (HMMA flash) ---
    const dim3 agrid(T_ / 128, BH_);
    attn_hmma<<<agrid, 256, ATT_SMEM>>>(qhi, qlo, khi, klo, vthi, vtlo, ahi, alo);

    // --- output projection ---
    hmma_gemm<0><<<ggrid, 256, GS_TOT>>>(ahi, alo,
        wT + 6 * (size_t)D_ * D_, wT + 7 * (size_t)D_ * D_, out, nullptr);
}